// round 10
// baseline (speedup 1.0000x reference)
#include <cuda_runtime.h>
#include <cuda_bf16.h>

// LIF neuron scan:
//   u[t] = tau * u[t-1] + x[t];  o[t] = (u[t] > 1);  u[t] *= (1 - o[t])
// x: [B, T, N] fp32, out: [B, T, N] fp32.  B=32, T=32, N=65536.
//
// R10: CHUNK=16 double-buffered chunk pipeline. Order:
//   read run A (16 LDG.128) -> read run B issued -> compute A -> store run A
//   -> compute B -> store run B
// So every warp keeps a full 16-load read run outstanding THROUGH its
// compute and store phases (R6's ptxas schedule, regs=122, provably did not
// hoist chunk-1 loads over chunk-0 compute). Store runs stay pure
// back-to-back STGs from float registers (R9 showed ALU ops between stores
// cost ~1.8% BW). ~150 regs -> 3 blocks/SM = 12 warps, each self-covering
// its compute gap.

#define T_STEPS 32
#define B_BATCH 32
#define CHUNK   16

__global__ __launch_bounds__(128) void lif_scan_kernel(
    const float4* __restrict__ x,
    const float*  __restrict__ tau_p,
    float4*       __restrict__ out,
    int nv,          // N/4 (float4 lanes per (b,t) row)
    int total)       // B * nv
{
    int i = blockIdx.x * blockDim.x + threadIdx.x;
    if (i >= total) return;

    // clamp learned decay to [0,1]
    float tau = __ldg(tau_p);
    tau = fminf(fmaxf(tau, 0.0f), 1.0f);

    int b = i / nv;          // nv is a power of two; compiler -> shift
    int j = i - b * nv;

    size_t base = (size_t)b * T_STEPS * nv + j;
    const float4* xb = x   + base;
    float4*       ob = out + base;

    const size_t half = (size_t)CHUNK * nv;

    // ---- read run A: 16 independent 16B loads, back-to-back ----
    float4 bufA[CHUNK];
#pragma unroll
    for (int t = 0; t < CHUNK; t++)
        bufA[t] = __ldcs(&xb[(size_t)t * nv]);

    // ---- read run B: issued immediately; in flight during compute A ----
    float4 bufB[CHUNK];
#pragma unroll
    for (int t = 0; t < CHUNK; t++)
        bufB[t] = __ldcs(&xb[half + (size_t)t * nv]);

    float ux = 0.0f, uy = 0.0f, uz = 0.0f, uw = 0.0f;

    // ---- compute A (consumes bufA, overwrites with outputs) ----
#pragma unroll
    for (int t = 0; t < CHUNK; t++) {
        float4 xi = bufA[t];

        ux = fmaf(tau, ux, xi.x);
        uy = fmaf(tau, uy, xi.y);
        uz = fmaf(tau, uz, xi.z);
        uw = fmaf(tau, uw, xi.w);

        float4 o;
        o.x = (ux > 1.0f) ? 1.0f : 0.0f;
        o.y = (uy > 1.0f) ? 1.0f : 0.0f;
        o.z = (uz > 1.0f) ? 1.0f : 0.0f;
        o.w = (uw > 1.0f) ? 1.0f : 0.0f;

        ux = (ux > 1.0f) ? 0.0f : ux;
        uy = (uy > 1.0f) ? 0.0f : uy;
        uz = (uz > 1.0f) ? 0.0f : uz;
        uw = (uw > 1.0f) ? 0.0f : uw;

        bufA[t] = o;
    }

    // ---- store run A: 16 back-to-back streaming stores ----
#pragma unroll
    for (int t = 0; t < CHUNK; t++)
        __stcs(&ob[(size_t)t * nv], bufA[t]);

    // ---- compute B ----
#pragma unroll
    for (int t = 0; t < CHUNK; t++) {
        float4 xi = bufB[t];

        ux = fmaf(tau, ux, xi.x);
        uy = fmaf(tau, uy, xi.y);
        uz = fmaf(tau, uz, xi.z);
        uw = fmaf(tau, uw, xi.w);

        float4 o;
        o.x = (ux > 1.0f) ? 1.0f : 0.0f;
        o.y = (uy > 1.0f) ? 1.0f : 0.0f;
        o.z = (uz > 1.0f) ? 1.0f : 0.0f;
        o.w = (uw > 1.0f) ? 1.0f : 0.0f;

        ux = (ux > 1.0f) ? 0.0f : ux;
        uy = (uy > 1.0f) ? 0.0f : uy;
        uz = (uz > 1.0f) ? 0.0f : uz;
        uw = (uw > 1.0f) ? 0.0f : uw;

        bufB[t] = o;
    }

    // ---- store run B: 16 back-to-back streaming stores ----
#pragma unroll
    for (int t = 0; t < CHUNK; t++)
        __stcs(&ob[half + (size_t)t * nv], bufB[t]);
}

extern "C" void kernel_launch(void* const* d_in, const int* in_sizes, int n_in,
                              void* d_out, int out_size)
{
    const float* x   = (const float*)d_in[0];   // [B, T, N] fp32
    const float* tau = (const float*)d_in[1];   // [1] fp32

    int total_elems = in_sizes[0];                       // B*T*N
    int N  = total_elems / (B_BATCH * T_STEPS);
    int nv = N / 4;                                      // float4 per (b,t) row
    int total_threads = B_BATCH * nv;                    // B * nv

    int block = 128;
    int grid  = (total_threads + block - 1) / block;

    lif_scan_kernel<<<grid, block>>>(
        (const float4*)x, tau, (float4*)d_out, nv, total_threads);
}

// round 11
// speedup vs baseline: 1.0425x; 1.0425x over previous
#include <cuda_runtime.h>
#include <cuda_bf16.h>

// LIF neuron scan:
//   u[t] = tau * u[t-1] + x[t];  o[t] = (u[t] > 1);  u[t] *= (1 - o[t])
// x: [B, T, N] fp32, out: [B, T, N] fp32.  B=32, T=32, N=65536.
//
// R11: cp.async (LDGSTS) pipeline — breaks the LDG register<->burst-depth
// coupling that capped R6 (burst16/14 warps/6242 GB/s best; burst32 collapsed
// to 7 warps/5857). Each thread fires all 32 16B cp.async.cg up front into a
// 64KB double-buffered smem tile (zero registers per outstanding load), then:
//   wait chunk0 -> compute from smem -> 16-store STG burst
//   wait chunk1 -> compute          -> 16-store STG burst
// Chunk1's loads are in flight THROUGH chunk0's compute+store -> continuous
// read coverage at ~512B/thread outstanding. Stores stay pure back-to-back
// (R9: ALU between stores costs BW). Occupancy smem-limited: 3 blocks/SM.

#define T_STEPS 32
#define B_BATCH 32
#define CHUNK   16
#define BLOCK   128

__device__ __forceinline__ void cp_async16(void* smem_dst, const void* gsrc, bool pred) {
    unsigned saddr = (unsigned)__cvta_generic_to_shared(smem_dst);
    if (pred)
        asm volatile("cp.async.cg.shared.global [%0], [%1], 16;\n"
                     :: "r"(saddr), "l"(gsrc));
}
__device__ __forceinline__ void cp_commit() {
    asm volatile("cp.async.commit_group;\n" ::: "memory");
}
template <int N>
__device__ __forceinline__ void cp_wait() {
    asm volatile("cp.async.wait_group %0;\n" :: "n"(N) : "memory");
}

__global__ __launch_bounds__(BLOCK) void lif_scan_kernel(
    const float4* __restrict__ x,
    const float*  __restrict__ tau_p,
    float4*       __restrict__ out,
    int nv,          // N/4 (float4 lanes per (b,t) row)
    int total)       // B * nv
{
    extern __shared__ float4 sbuf[];   // [2][CHUNK][BLOCK] = 64 KB

    int tid = threadIdx.x;
    int i   = blockIdx.x * BLOCK + tid;
    bool active = (i < total);
    int  ii = active ? i : 0;          // safe index for inactive threads

    // clamp learned decay to [0,1]
    float tau = __ldg(tau_p);
    tau = fminf(fmaxf(tau, 0.0f), 1.0f);

    int b = ii / nv;                   // nv is a power of two; compiler -> shift
    int j = ii - b * nv;

    size_t base = (size_t)b * T_STEPS * nv + j;
    const float4* xb = x   + base;
    float4*       ob = out + base;

    // ---- fire ALL 32 loads up front (register-free outstanding reads) ----
#pragma unroll
    for (int t = 0; t < CHUNK; t++)
        cp_async16(&sbuf[t * BLOCK + tid], &xb[(size_t)t * nv], active);
    cp_commit();                                            // group: chunk 0
#pragma unroll
    for (int t = 0; t < CHUNK; t++)
        cp_async16(&sbuf[(CHUNK + t) * BLOCK + tid],
                   &xb[(size_t)(CHUNK + t) * nv], active);
    cp_commit();                                            // group: chunk 1

    float ux = 0.0f, uy = 0.0f, uz = 0.0f, uw = 0.0f;
    float4 oreg[CHUNK];

    // ================= chunk 0 =================
    cp_wait<1>();            // chunk 0 landed (chunk 1 still in flight)
    __syncthreads();

#pragma unroll
    for (int t = 0; t < CHUNK; t++) {
        float4 xi = sbuf[t * BLOCK + tid];

        ux = fmaf(tau, ux, xi.x);
        uy = fmaf(tau, uy, xi.y);
        uz = fmaf(tau, uz, xi.z);
        uw = fmaf(tau, uw, xi.w);

        float4 o;
        o.x = (ux > 1.0f) ? 1.0f : 0.0f;
        o.y = (uy > 1.0f) ? 1.0f : 0.0f;
        o.z = (uz > 1.0f) ? 1.0f : 0.0f;
        o.w = (uw > 1.0f) ? 1.0f : 0.0f;

        ux = (ux > 1.0f) ? 0.0f : ux;
        uy = (uy > 1.0f) ? 0.0f : uy;
        uz = (uz > 1.0f) ? 0.0f : uz;
        uw = (uw > 1.0f) ? 0.0f : uw;

        oreg[t] = o;
    }

    // pure back-to-back streaming store run (chunk 1 loads still in flight)
    if (active) {
#pragma unroll
        for (int t = 0; t < CHUNK; t++)
            __stcs(&ob[(size_t)t * nv], oreg[t]);
    }

    // ================= chunk 1 =================
    cp_wait<0>();
    __syncthreads();

#pragma unroll
    for (int t = 0; t < CHUNK; t++) {
        float4 xi = sbuf[(CHUNK + t) * BLOCK + tid];

        ux = fmaf(tau, ux, xi.x);
        uy = fmaf(tau, uy, xi.y);
        uz = fmaf(tau, uz, xi.z);
        uw = fmaf(tau, uw, xi.w);

        float4 o;
        o.x = (ux > 1.0f) ? 1.0f : 0.0f;
        o.y = (uy > 1.0f) ? 1.0f : 0.0f;
        o.z = (uz > 1.0f) ? 1.0f : 0.0f;
        o.w = (uw > 1.0f) ? 1.0f : 0.0f;

        ux = (ux > 1.0f) ? 0.0f : ux;
        uy = (uy > 1.0f) ? 0.0f : uy;
        uz = (uz > 1.0f) ? 0.0f : uz;
        uw = (uw > 1.0f) ? 0.0f : uw;

        oreg[t] = o;
    }

    if (active) {
#pragma unroll
        for (int t = 0; t < CHUNK; t++)
            __stcs(&ob[(size_t)(CHUNK + t) * nv], oreg[t]);
    }
}

extern "C" void kernel_launch(void* const* d_in, const int* in_sizes, int n_in,
                              void* d_out, int out_size)
{
    const float* x   = (const float*)d_in[0];   // [B, T, N] fp32
    const float* tau = (const float*)d_in[1];   // [1] fp32

    int total_elems = in_sizes[0];                       // B*T*N
    int N  = total_elems / (B_BATCH * T_STEPS);
    int nv = N / 4;                                      // float4 per (b,t) row
    int total_threads = B_BATCH * nv;                    // B * nv

    const int smem_bytes = 2 * CHUNK * BLOCK * (int)sizeof(float4);  // 64 KB

    // opt-in for >48KB dynamic smem (idempotent; not a stream op, capture-safe)
    cudaFuncSetAttribute(lif_scan_kernel,
                         cudaFuncAttributeMaxDynamicSharedMemorySize, smem_bytes);

    int grid = (total_threads + BLOCK - 1) / BLOCK;

    lif_scan_kernel<<<grid, BLOCK, smem_bytes>>>(
        (const float4*)x, tau, (float4*)d_out, nv, total_threads);
}